// round 8
// baseline (speedup 1.0000x reference)
#include <cuda_runtime.h>
#include <math.h>

// ---------------------------------------------------------------------------
// SmoothAP (quick_forward, sigmoid rank approx, 1-mAP), B x B scores/target.
//
//   ap[b] = (1/npos_b) * sum_{i : target[b,i]=1} sim_pos_i / sim_all_i
// Using sigmoid(y) = 0.5*(1 + tanh(y/2)), scores pre-scaled by 1/(2*tau):
//   T_i  = sum_j tanh(50*(s_j - s_i))          (all j; diag tanh(0)=0)
//   Tp_i = sum_j tanh(50*(s_j - s_i)) * tg_j
//   ratio_i = (Tp_i + np + 1) / (T_i + B + 1)  (np = #positives incl. diag)
//   out = 1 - (1/B) * mean_b ( sum_i ratio_i / np )
//
// Single fused kernel, 2 positives per warp-iteration (4 accumulator chains),
// reg-capped for 6 blocks/SM so the whole grid is resident in one wave.
// ---------------------------------------------------------------------------

#define KSCALE 50.0f        // 1/(2*tau)
#define MAX_B  2048

__device__ float        g_partial[MAX_B];
__device__ float        g_accum;          // generic fallback only
__device__ unsigned int g_count = 0;      // ticket counter; re-armed each run

__device__ __forceinline__ float tanha(float x) {
    float r; asm("tanh.approx.f32 %0, %1;" : "=f"(r) : "f"(x)); return r;
}
__device__ __forceinline__ float ex2a(float x) {
    float r; asm("ex2.approx.f32 %0, %1;" : "=f"(r) : "f"(x)); return r;
}
__device__ __forceinline__ float rcpa(float x) {
    float r; asm("rcp.approx.f32 %0, %1;" : "=f"(r) : "f"(x)); return r;
}

// ---------------- fused kernel: B == 512, 256 threads, 1 row/block ----------
__global__ void __launch_bounds__(256, 6)
sap512_fused(const float* __restrict__ scores,
             const float* __restrict__ target,
             float* __restrict__ out) {
    constexpr int B  = 512;
    constexpr int NW = 8;                  // warps per block
    __shared__ __align__(16) float ssK[B]; // scores row * KSCALE
    __shared__ __align__(16) float st[B];  // target row
    __shared__ float wsum[NW];
    __shared__ int   wcnt[2 * NW];
    __shared__ short plist[B];
    __shared__ bool  isLast;

    const int b    = blockIdx.x;
    const int tid  = threadIdx.x;
    const int lane = tid & 31;
    const int warp = tid >> 5;

    const float* srow = scores + (size_t)b * B;
    const float* trow = target + (size_t)b * B;
    ssK[tid]       = srow[tid]       * KSCALE;
    ssK[tid + 256] = srow[tid + 256] * KSCALE;
    st[tid]        = trow[tid];
    st[tid + 256]  = trow[tid + 256];
    __syncthreads();

    // ---- deterministic compaction of positive i's (16 groups of 32) -------
    const bool p0 = (st[tid]       != 0.0f);
    const bool p1 = (st[tid + 256] != 0.0f);
    const unsigned m0 = __ballot_sync(0xffffffffu, p0);
    const unsigned m1 = __ballot_sync(0xffffffffu, p1);
    if (lane == 0) { wcnt[warp] = __popc(m0); wcnt[NW + warp] = __popc(m1); }
    __syncthreads();

    int c   = (lane < 2 * NW) ? wcnt[lane] : 0;
    int inc = c;
#pragma unroll
    for (int o = 1; o < 16; o <<= 1) {
        int t = __shfl_up_sync(0xffffffffu, inc, o);
        if (lane >= o) inc += t;
    }
    const int total   = __shfl_sync(0xffffffffu, inc, 15);  // np (incl. diag)
    const int exc     = inc - c;
    const int before0 = __shfl_sync(0xffffffffu, exc, warp);
    const int before1 = __shfl_sync(0xffffffffu, exc, NW + warp);
    const unsigned lt = (1u << lane) - 1u;
    if (p0) plist[before0 + __popc(m0 & lt)] = (short)tid;
    if (p1) plist[before1 + __popc(m1 & lt)] = (short)(tid + 256);
    __syncthreads();

    // ---- main loop: TWO positives per warp-iteration (4 accum chains) ------
    const float4* ss4 = (const float4*)ssK;
    const float4* st4 = (const float4*)st;
    const float numc = (float)(total + 1);        // np + 1
    const float denc = (float)(B + 1);            // 513
    float sum_r = 0.0f;
    for (int k = warp * 2; k < total; k += NW * 2) {
        const bool  has2 = (k + 1 < total);
        const float si1  = ssK[plist[k]];
        const float si2  = ssK[plist[has2 ? k + 1 : k]];
        float T1 = 0.0f, P1 = 0.0f, T2 = 0.0f, P2 = 0.0f;
#pragma unroll
        for (int q = 0; q < B / 128; ++q) {
            float4 s4 = ss4[q * 32 + lane];
            float4 t4 = st4[q * 32 + lane];
            float a0 = tanha(s4.x - si1), b0 = tanha(s4.x - si2);
            float a1 = tanha(s4.y - si1), b1 = tanha(s4.y - si2);
            float a2 = tanha(s4.z - si1), b2 = tanha(s4.z - si2);
            float a3 = tanha(s4.w - si1), b3 = tanha(s4.w - si2);
            T1 += (a0 + a1) + (a2 + a3);
            T2 += (b0 + b1) + (b2 + b3);
            P1 = fmaf(a0, t4.x, fmaf(a1, t4.y, fmaf(a2, t4.z, fmaf(a3, t4.w, P1))));
            P2 = fmaf(b0, t4.x, fmaf(b1, t4.y, fmaf(b2, t4.z, fmaf(b3, t4.w, P2))));
        }
#pragma unroll
        for (int o = 16; o; o >>= 1) {
            T1 += __shfl_xor_sync(0xffffffffu, T1, o);
            T2 += __shfl_xor_sync(0xffffffffu, T2, o);
            P1 += __shfl_xor_sync(0xffffffffu, P1, o);
            P2 += __shfl_xor_sync(0xffffffffu, P2, o);
        }
        sum_r += __fdividef(P1 + numc, T1 + denc);
        if (has2) sum_r += __fdividef(P2 + numc, T2 + denc);
    }
    if (lane == 0) wsum[warp] = sum_r;
    __syncthreads();

    // ---- block reduce, publish partial, grab ticket ------------------------
    if (warp == 0) {
        float bs = (lane < NW) ? wsum[lane] : 0.0f;
#pragma unroll
        for (int o = 4; o; o >>= 1) bs += __shfl_xor_sync(0xffffffffu, bs, o);
        if (lane == 0) {
            g_partial[b] = __fdividef(bs, (float)total);
            __threadfence();
            unsigned old = atomicAdd(&g_count, 1u);
            isLast = (old == (unsigned)(gridDim.x - 1));
        }
    }
    __syncthreads();

    // ---- last block: reduce 512 partials, write output, re-arm -------------
    if (isLast) {
        float v = __ldcg(&g_partial[tid]) + __ldcg(&g_partial[tid + 256]);
#pragma unroll
        for (int o = 16; o; o >>= 1) v += __shfl_xor_sync(0xffffffffu, v, o);
        if (lane == 0) wsum[warp] = v;
        __syncthreads();
        if (warp == 0) {
            float t = (lane < NW) ? wsum[lane] : 0.0f;
#pragma unroll
            for (int o = 4; o; o >>= 1) t += __shfl_xor_sync(0xffffffffu, t, o);
            if (lane == 0) {
                out[0] = 1.0f - t * (1.0f / 512.0f);
                atomicExch(&g_count, 0u);     // re-arm for next graph replay
            }
        }
    }
}

// ---------------- generic fallback (any B) ----------------------------------
__global__ void sap_generic_kernel(const float* __restrict__ scores,
                                   const float* __restrict__ target,
                                   float* __restrict__ out, int B) {
    extern __shared__ float sh[];
    float* ss   = sh;
    float* st   = sh + B;
    float* wred = sh + 2 * B;
    __shared__ bool isLast;

    const int b      = blockIdx.x;
    const int tid    = threadIdx.x;
    const int lane   = tid & 31;
    const int warp   = tid >> 5;
    const int nwarps = blockDim.x >> 5;

    const float* srow = scores + (size_t)b * B;
    const float* trow = target + (size_t)b * B;
    for (int j = tid; j < B; j += blockDim.x) {
        ss[j] = srow[j] * 144.26950408889634f;   // (1/tau)*log2e
        st[j] = trow[j];
    }
    __syncthreads();

    float sum_r = 0.0f;
    for (int i = warp; i < B; i += nwarps) {
        if (st[i] == 0.0f) continue;
        const float siK = ss[i];
        float A = 0.0f, P = 0.0f;
        for (int j = lane; j < B; j += 32) {
            float g = rcpa(1.0f + ex2a(siK - ss[j]));
            A += g;
            P = fmaf(g, st[j], P);
        }
#pragma unroll
        for (int o = 16; o; o >>= 1) {
            A += __shfl_xor_sync(0xffffffffu, A, o);
            P += __shfl_xor_sync(0xffffffffu, P, o);
        }
        sum_r += __fdividef(P + 0.5f, A + 0.5f);
    }
    if (lane == 0) wred[warp] = sum_r;
    __syncthreads();

    if (warp == 0) {
        float np = 0.0f;
        for (int j = lane; j < B; j += 32) np += st[j];
#pragma unroll
        for (int o = 16; o; o >>= 1) np += __shfl_xor_sync(0xffffffffu, np, o);
        float bs = (lane < nwarps) ? wred[lane] : 0.0f;
#pragma unroll
        for (int o = 16; o; o >>= 1) bs += __shfl_xor_sync(0xffffffffu, bs, o);
        if (lane == 0) {
            atomicAdd(&g_accum, __fdividef(bs, np));
            __threadfence();
            unsigned old = atomicAdd(&g_count, 1u);
            isLast = (old == (unsigned)gridDim.x - 1u);
        }
    }
    __syncthreads();
    if (isLast && tid == 0) {
        float tot = atomicAdd(&g_accum, 0.0f);
        out[0] = 1.0f - tot / (float)B;
        atomicExch(&g_accum, 0.0f);
        atomicExch(&g_count, 0u);
    }
}

extern "C" void kernel_launch(void* const* d_in, const int* in_sizes, int n_in,
                              void* d_out, int out_size) {
    const float* scores = (const float*)d_in[0];
    const float* target = (const float*)d_in[1];
    float* out = (float*)d_out;

    int n = in_sizes[0];
    int B = 1;
    while ((long long)B * B < (long long)n) ++B;

    if (B == 512) {
        sap512_fused<<<512, 256>>>(scores, target, out);
    } else {
        int threads = 512;
        if (threads > B) {
            threads = ((B + 31) / 32) * 32;
            if (threads < 32) threads = 32;
        }
        size_t smem = (size_t)2 * B * sizeof(float) + 32 * sizeof(float);
        sap_generic_kernel<<<B, threads, smem>>>(scores, target, out, B);
    }
}

// round 9
// speedup vs baseline: 1.1254x; 1.1254x over previous
#include <cuda_runtime.h>
#include <math.h>

// ---------------------------------------------------------------------------
// SmoothAP (quick_forward, sigmoid rank approx, 1-mAP), B x B scores/target.
//
//   ap[b] = (1/np_b) * sum_{i in pos(b)} (Tp_i + np + 1) / (T_i + B + 1)
//   T_i  = sum_j       tanh(50*(s_j - s_i))     (diag tanh(0)=0)
//   Tp_i = sum_{j in pos} tanh(50*(s_j - s_i))  (target is 0/1 -> sum over
//                                                the compacted positive list)
//   out = 1 - mean_b ap[b]
//
// Layout: one block per row b.  Positives compacted into plist.  Each lane of
// every warp owns one positive (npos <= 32 per group); warps split the j-range
// into 64-j chunks streamed as broadcast float4 LDS.  Warp 0 combines the 8
// per-warp partials, adds the positive-only Tp sum, reduces ratios.
// Single fused kernel; last block (ticket) reduces g_partial.  Deterministic.
// ---------------------------------------------------------------------------

#define KSCALE 50.0f        // 1/(2*tau)
#define MAX_B  2048

__device__ float        g_partial[MAX_B];
__device__ float        g_accum;          // generic fallback only
__device__ unsigned int g_count = 0;      // ticket counter; re-armed each run

__device__ __forceinline__ float tanha(float x) {
    float r; asm("tanh.approx.f32 %0, %1;" : "=f"(r) : "f"(x)); return r;
}
__device__ __forceinline__ float ex2a(float x) {
    float r; asm("ex2.approx.f32 %0, %1;" : "=f"(r) : "f"(x)); return r;
}
__device__ __forceinline__ float rcpa(float x) {
    float r; asm("rcp.approx.f32 %0, %1;" : "=f"(r) : "f"(x)); return r;
}

// ---------------- fused kernel: B == 512, 256 threads, 1 row/block ----------
__global__ void __launch_bounds__(256)
sap512_fused(const float* __restrict__ scores,
             const float* __restrict__ target,
             float* __restrict__ out) {
    constexpr int B  = 512;
    constexpr int NW = 8;                   // warps per block
    __shared__ __align__(16) float ssK[B];  // scores row * KSCALE
    __shared__ float wT[NW][32];            // per-warp T partials per lane-pos
    __shared__ float sposAll[B];            // scores of compacted positives
    __shared__ short plist[B];
    __shared__ int   wcnt[2 * NW];
    __shared__ float red[NW];
    __shared__ bool  isLast;

    const int b    = blockIdx.x;
    const int tid  = threadIdx.x;
    const int lane = tid & 31;
    const int warp = tid >> 5;

    const float* srow = scores + (size_t)b * B;
    const float* trow = target + (size_t)b * B;
    ssK[tid]       = srow[tid]       * KSCALE;
    ssK[tid + 256] = srow[tid + 256] * KSCALE;
    const float tg0 = trow[tid];
    const float tg1 = trow[tid + 256];

    // ---- deterministic compaction of positive i's (16 groups of 32) -------
    const bool p0 = (tg0 != 0.0f);
    const bool p1 = (tg1 != 0.0f);
    const unsigned m0 = __ballot_sync(0xffffffffu, p0);
    const unsigned m1 = __ballot_sync(0xffffffffu, p1);
    if (lane == 0) { wcnt[warp] = __popc(m0); wcnt[NW + warp] = __popc(m1); }
    __syncthreads();                        // wcnt + ssK visible

    int c   = (lane < 2 * NW) ? wcnt[lane] : 0;
    int inc = c;
#pragma unroll
    for (int o = 1; o < 16; o <<= 1) {
        int t = __shfl_up_sync(0xffffffffu, inc, o);
        if (lane >= o) inc += t;
    }
    const int total   = __shfl_sync(0xffffffffu, inc, 15);  // np (incl. diag)
    const int exc     = inc - c;
    const int before0 = __shfl_sync(0xffffffffu, exc, warp);
    const int before1 = __shfl_sync(0xffffffffu, exc, NW + warp);
    const unsigned lt = (1u << lane) - 1u;
    if (p0) plist[before0 + __popc(m0 & lt)] = (short)tid;
    if (p1) plist[before1 + __popc(m1 & lt)] = (short)(tid + 256);
    __syncthreads();                        // plist ready

    if (tid < total) sposAll[tid] = ssK[plist[tid]];
    __syncthreads();                        // sposAll ready

    // ---- main: lane-per-positive, warp-per-j-chunk -------------------------
    const float4* ss4 = (const float4*)ssK;
    const float np1   = (float)(total + 1);
    float blocksum = 0.0f;                  // meaningful in warp 0

    for (int pb = 0; pb < total; pb += 32) {
        const int   npg = (total - pb < 32) ? (total - pb) : 32;
        const float si  = sposAll[pb + ((lane < npg) ? lane : 0)];

        float Tp = 0.0f;
#pragma unroll
        for (int q = 0; q < 16; ++q) {      // 64 j's per warp, broadcast LDS
            float4 s4 = ss4[warp * 16 + q];
            Tp += (tanha(s4.x - si) + tanha(s4.y - si))
                + (tanha(s4.z - si) + tanha(s4.w - si));
        }
        wT[warp][lane] = Tp;
        __syncthreads();

        if (warp == 0) {
            float T = 0.0f;
#pragma unroll
            for (int w = 0; w < NW; ++w) T += wT[w][lane];
            float P = 0.0f;
#pragma unroll 4
            for (int kk = 0; kk < total; ++kk)
                P += tanha(sposAll[kk] - si);
            float r = __fdividef(P + np1, T + (float)(B + 1));
            r = (lane < npg) ? r : 0.0f;
#pragma unroll
            for (int o = 16; o; o >>= 1) r += __shfl_xor_sync(0xffffffffu, r, o);
            blocksum += r;
        }
        __syncthreads();                    // protect wT for next group
    }

    // ---- publish partial, grab ticket --------------------------------------
    if (tid == 0) {
        g_partial[b] = __fdividef(blocksum, (float)total);
        __threadfence();
        unsigned old = atomicAdd(&g_count, 1u);
        isLast = (old == (unsigned)(gridDim.x - 1));
    }
    __syncthreads();

    // ---- last block: reduce 512 partials, write output, re-arm -------------
    if (isLast) {
        float v = __ldcg(&g_partial[tid]) + __ldcg(&g_partial[tid + 256]);
#pragma unroll
        for (int o = 16; o; o >>= 1) v += __shfl_xor_sync(0xffffffffu, v, o);
        if (lane == 0) red[warp] = v;
        __syncthreads();
        if (warp == 0) {
            float t = (lane < NW) ? red[lane] : 0.0f;
#pragma unroll
            for (int o = 4; o; o >>= 1) t += __shfl_xor_sync(0xffffffffu, t, o);
            if (lane == 0) {
                out[0] = 1.0f - t * (1.0f / 512.0f);
                atomicExch(&g_count, 0u);   // re-arm for next graph replay
            }
        }
    }
}

// ---------------- generic fallback (any B) ----------------------------------
__global__ void sap_generic_kernel(const float* __restrict__ scores,
                                   const float* __restrict__ target,
                                   float* __restrict__ out, int B) {
    extern __shared__ float sh[];
    float* ss   = sh;
    float* st   = sh + B;
    float* wred = sh + 2 * B;
    __shared__ bool isLast;

    const int b      = blockIdx.x;
    const int tid    = threadIdx.x;
    const int lane   = tid & 31;
    const int warp   = tid >> 5;
    const int nwarps = blockDim.x >> 5;

    const float* srow = scores + (size_t)b * B;
    const float* trow = target + (size_t)b * B;
    for (int j = tid; j < B; j += blockDim.x) {
        ss[j] = srow[j] * 144.26950408889634f;   // (1/tau)*log2e
        st[j] = trow[j];
    }
    __syncthreads();

    float sum_r = 0.0f;
    for (int i = warp; i < B; i += nwarps) {
        if (st[i] == 0.0f) continue;
        const float siK = ss[i];
        float A = 0.0f, P = 0.0f;
        for (int j = lane; j < B; j += 32) {
            float g = rcpa(1.0f + ex2a(siK - ss[j]));
            A += g;
            P = fmaf(g, st[j], P);
        }
#pragma unroll
        for (int o = 16; o; o >>= 1) {
            A += __shfl_xor_sync(0xffffffffu, A, o);
            P += __shfl_xor_sync(0xffffffffu, P, o);
        }
        sum_r += __fdividef(P + 0.5f, A + 0.5f);
    }
    if (lane == 0) wred[warp] = sum_r;
    __syncthreads();

    if (warp == 0) {
        float np = 0.0f;
        for (int j = lane; j < B; j += 32) np += st[j];
#pragma unroll
        for (int o = 16; o; o >>= 1) np += __shfl_xor_sync(0xffffffffu, np, o);
        float bs = (lane < nwarps) ? wred[lane] : 0.0f;
#pragma unroll
        for (int o = 16; o; o >>= 1) bs += __shfl_xor_sync(0xffffffffu, bs, o);
        if (lane == 0) {
            atomicAdd(&g_accum, __fdividef(bs, np));
            __threadfence();
            unsigned old = atomicAdd(&g_count, 1u);
            isLast = (old == (unsigned)gridDim.x - 1u);
        }
    }
    __syncthreads();
    if (isLast && tid == 0) {
        float tot = atomicAdd(&g_accum, 0.0f);
        out[0] = 1.0f - tot / (float)B;
        atomicExch(&g_accum, 0.0f);
        atomicExch(&g_count, 0u);
    }
}

extern "C" void kernel_launch(void* const* d_in, const int* in_sizes, int n_in,
                              void* d_out, int out_size) {
    const float* scores = (const float*)d_in[0];
    const float* target = (const float*)d_in[1];
    float* out = (float*)d_out;

    int n = in_sizes[0];
    int B = 1;
    while ((long long)B * B < (long long)n) ++B;

    if (B == 512) {
        sap512_fused<<<512, 256>>>(scores, target, out);
    } else {
        int threads = 512;
        if (threads > B) {
            threads = ((B + 31) / 32) * 32;
            if (threads < 32) threads = 32;
        }
        size_t smem = (size_t)2 * B * sizeof(float) + 32 * sizeof(float);
        sap_generic_kernel<<<B, threads, smem>>>(scores, target, out, B);
    }
}

// round 10
// speedup vs baseline: 1.1745x; 1.0436x over previous
#include <cuda_runtime.h>
#include <math.h>

// ---------------------------------------------------------------------------
// SmoothAP (quick_forward, sigmoid rank approx, 1-mAP), B x B scores/target.
//
//   ap[b] = (1/np_b) * sum_{i in pos(b)} (Tp_i + np + 1) / (T_i + B + 1)
//   T_i  = sum_j tanh(50*(s_j - s_i))            (diag tanh(0)=0)
//   Tp_i = sum_j tanh(50*(s_j - s_i)) * tg_j
//   out  = 1 - mean_b ap[b]
//
// One block per row.  j-parallel across lanes (pair-optimal MUFU count:
// npos*B lane-pairs, no wasted tanh), 2 positives per warp trip for ILP.
// Blocks atomicAdd ap_b into g_accum; ticketed last block writes out and
// re-arms.  Single launch, graph-capturable, allocation-free.
// ---------------------------------------------------------------------------

#define KSCALE 50.0f        // 1/(2*tau)

__device__ float        g_accum;          // zero at load; re-armed each run
__device__ unsigned int g_count = 0;      // ticket counter; re-armed each run

__device__ __forceinline__ float tanha(float x) {
    float r; asm("tanh.approx.f32 %0, %1;" : "=f"(r) : "f"(x)); return r;
}
__device__ __forceinline__ float ex2a(float x) {
    float r; asm("ex2.approx.f32 %0, %1;" : "=f"(r) : "f"(x)); return r;
}
__device__ __forceinline__ float rcpa(float x) {
    float r; asm("rcp.approx.f32 %0, %1;" : "=f"(r) : "f"(x)); return r;
}

// ---------------- fused kernel: B == 512, 256 threads, 1 row/block ----------
__global__ void __launch_bounds__(256)
sap512_fused(const float* __restrict__ scores,
             const float* __restrict__ target,
             float* __restrict__ out) {
    constexpr int B  = 512;
    constexpr int NW = 8;                   // warps per block
    __shared__ __align__(16) float ssK[B];  // scores row * KSCALE
    __shared__ __align__(16) float st[B];   // target row
    __shared__ float wsum[NW];
    __shared__ int   wcnt[2 * NW];
    __shared__ short plist[B];
    __shared__ bool  isLast;

    const int b    = blockIdx.x;
    const int tid  = threadIdx.x;
    const int lane = tid & 31;
    const int warp = tid >> 5;

    // ---- prologue: one LDG.128 per thread ----------------------------------
    {
        const float4* s4g = (const float4*)(scores + (size_t)b * B);
        const float4* t4g = (const float4*)(target + (size_t)b * B);
        if (tid < 128) {
            float4 v = s4g[tid];
            ((float4*)ssK)[tid] = make_float4(v.x * KSCALE, v.y * KSCALE,
                                              v.z * KSCALE, v.w * KSCALE);
        } else {
            ((float4*)st)[tid - 128] = t4g[tid - 128];
        }
    }
    __syncthreads();

    // ---- deterministic compaction of positive i's (16 groups of 32) -------
    const bool p0 = (st[tid]       != 0.0f);
    const bool p1 = (st[tid + 256] != 0.0f);
    const unsigned m0 = __ballot_sync(0xffffffffu, p0);
    const unsigned m1 = __ballot_sync(0xffffffffu, p1);
    if (lane == 0) { wcnt[warp] = __popc(m0); wcnt[NW + warp] = __popc(m1); }
    __syncthreads();

    int c   = (lane < 2 * NW) ? wcnt[lane] : 0;
    int inc = c;
#pragma unroll
    for (int o = 1; o < 16; o <<= 1) {
        int t = __shfl_up_sync(0xffffffffu, inc, o);
        if (lane >= o) inc += t;
    }
    const int total   = __shfl_sync(0xffffffffu, inc, 15);  // np (incl. diag)
    const int exc     = inc - c;
    const int before0 = __shfl_sync(0xffffffffu, exc, warp);
    const int before1 = __shfl_sync(0xffffffffu, exc, NW + warp);
    const unsigned lt = (1u << lane) - 1u;
    if (p0) plist[before0 + __popc(m0 & lt)] = (short)tid;
    if (p1) plist[before1 + __popc(m1 & lt)] = (short)(tid + 256);
    __syncthreads();

    // ---- main: TWO positives per warp trip, j-parallel across lanes --------
    const float4* ss4 = (const float4*)ssK;
    const float4* st4 = (const float4*)st;
    const float numc = (float)(total + 1);        // np + 1
    const float denc = (float)(B + 1);            // 513
    float sum_r = 0.0f;
    for (int k = warp * 2; k < total; k += NW * 2) {
        const bool  has2 = (k + 1 < total);
        const float si1  = ssK[plist[k]];
        const float si2  = ssK[plist[has2 ? k + 1 : k]];
        float T1 = 0.0f, P1 = 0.0f, T2 = 0.0f, P2 = 0.0f;
#pragma unroll
        for (int q = 0; q < B / 128; ++q) {
            float4 s4 = ss4[q * 32 + lane];
            float4 t4 = st4[q * 32 + lane];
            float a0 = tanha(s4.x - si1), b0 = tanha(s4.x - si2);
            float a1 = tanha(s4.y - si1), b1 = tanha(s4.y - si2);
            float a2 = tanha(s4.z - si1), b2 = tanha(s4.z - si2);
            float a3 = tanha(s4.w - si1), b3 = tanha(s4.w - si2);
            T1 += (a0 + a1) + (a2 + a3);
            T2 += (b0 + b1) + (b2 + b3);
            P1 = fmaf(a0, t4.x, fmaf(a1, t4.y, fmaf(a2, t4.z, fmaf(a3, t4.w, P1))));
            P2 = fmaf(b0, t4.x, fmaf(b1, t4.y, fmaf(b2, t4.z, fmaf(b3, t4.w, P2))));
        }
#pragma unroll
        for (int o = 16; o; o >>= 1) {
            T1 += __shfl_xor_sync(0xffffffffu, T1, o);
            T2 += __shfl_xor_sync(0xffffffffu, T2, o);
            P1 += __shfl_xor_sync(0xffffffffu, P1, o);
            P2 += __shfl_xor_sync(0xffffffffu, P2, o);
        }
        sum_r += __fdividef(P1 + numc, T1 + denc);
        if (has2) sum_r += __fdividef(P2 + numc, T2 + denc);
    }
    if (lane == 0) wsum[warp] = sum_r;
    __syncthreads();

    // ---- block reduce -> one float atomicAdd, grab ticket ------------------
    if (warp == 0) {
        float bs = (lane < NW) ? wsum[lane] : 0.0f;
#pragma unroll
        for (int o = 4; o; o >>= 1) bs += __shfl_xor_sync(0xffffffffu, bs, o);
        if (lane == 0) {
            atomicAdd(&g_accum, __fdividef(bs, (float)total));
            __threadfence();
            unsigned old = atomicAdd(&g_count, 1u);
            isLast = (old == (unsigned)(gridDim.x - 1));
        }
    }
    __syncthreads();

    // ---- last block: finalize + re-arm for next graph replay ---------------
    if (isLast && tid == 0) {
        __threadfence();
        float tot = atomicAdd(&g_accum, 0.0f);   // coherent L2 read
        out[0] = 1.0f - tot * (1.0f / 512.0f);
        atomicExch(&g_accum, 0.0f);
        atomicExch(&g_count, 0u);
    }
}

// ---------------- generic fallback (any B) ----------------------------------
__global__ void sap_generic_kernel(const float* __restrict__ scores,
                                   const float* __restrict__ target,
                                   float* __restrict__ out, int B) {
    extern __shared__ float sh[];
    float* ss   = sh;
    float* st   = sh + B;
    float* wred = sh + 2 * B;
    __shared__ bool isLast;

    const int b      = blockIdx.x;
    const int tid    = threadIdx.x;
    const int lane   = tid & 31;
    const int warp   = tid >> 5;
    const int nwarps = blockDim.x >> 5;

    const float* srow = scores + (size_t)b * B;
    const float* trow = target + (size_t)b * B;
    for (int j = tid; j < B; j += blockDim.x) {
        ss[j] = srow[j] * 144.26950408889634f;   // (1/tau)*log2e
        st[j] = trow[j];
    }
    __syncthreads();

    float sum_r = 0.0f;
    for (int i = warp; i < B; i += nwarps) {
        if (st[i] == 0.0f) continue;
        const float siK = ss[i];
        float A = 0.0f, P = 0.0f;
        for (int j = lane; j < B; j += 32) {
            float g = rcpa(1.0f + ex2a(siK - ss[j]));
            A += g;
            P = fmaf(g, st[j], P);
        }
#pragma unroll
        for (int o = 16; o; o >>= 1) {
            A += __shfl_xor_sync(0xffffffffu, A, o);
            P += __shfl_xor_sync(0xffffffffu, P, o);
        }
        sum_r += __fdividef(P + 0.5f, A + 0.5f);
    }
    if (lane == 0) wred[warp] = sum_r;
    __syncthreads();

    if (warp == 0) {
        float np = 0.0f;
        for (int j = lane; j < B; j += 32) np += st[j];
#pragma unroll
        for (int o = 16; o; o >>= 1) np += __shfl_xor_sync(0xffffffffu, np, o);
        float bs = (lane < nwarps) ? wred[lane] : 0.0f;
#pragma unroll
        for (int o = 16; o; o >>= 1) bs += __shfl_xor_sync(0xffffffffu, bs, o);
        if (lane == 0) {
            atomicAdd(&g_accum, __fdividef(bs, np));
            __threadfence();
            unsigned old = atomicAdd(&g_count, 1u);
            isLast = (old == (unsigned)gridDim.x - 1u);
        }
    }
    __syncthreads();
    if (isLast && tid == 0) {
        __threadfence();
        float tot = atomicAdd(&g_accum, 0.0f);
        out[0] = 1.0f - tot / (float)B;
        atomicExch(&g_accum, 0.0f);
        atomicExch(&g_count, 0u);
    }
}

extern "C" void kernel_launch(void* const* d_in, const int* in_sizes, int n_in,
                              void* d_out, int out_size) {
    const float* scores = (const float*)d_in[0];
    const float* target = (const float*)d_in[1];
    float* out = (float*)d_out;

    int n = in_sizes[0];
    int B = 1;
    while ((long long)B * B < (long long)n) ++B;

    if (B == 512) {
        sap512_fused<<<512, 256>>>(scores, target, out);
    } else {
        int threads = 512;
        if (threads > B) {
            threads = ((B + 31) / 32) * 32;
            if (threads < 32) threads = 32;
        }
        size_t smem = (size_t)2 * B * sizeof(float) + 32 * sizeof(float);
        sap_generic_kernel<<<B, threads, smem>>>(scores, target, out, B);
    }
}